// round 12
// baseline (speedup 1.0000x reference)
#include <cuda_runtime.h>
#include <cuda_fp16.h>

#define Bb 8
#define Nn 4096
#define Cc 128
#define Kk 20

// ------------------------- scratch (device globals, no allocs) -------------
__device__ int    g_knn[Bb*Nn*Kk];        // 20 neighbor indices per point (global b*N+n space)
__device__ float  g_wT[2*Cc*Cc];          // WcT then WgT, [c][o]
__device__ float  g_center[Bb*Cc*Nn];     // Wc @ leaky(p)         [b][o][n]
__device__ __half g_hT[Bb*Nn*Cc];         // (Wg @ leaky(p))^T in fp16  [b][n][o]

// ------------------------- prep: transpose weights -------------------------
__global__ __launch_bounds__(256) void prep_kernel(const float* __restrict__ Wc,
                                                   const float* __restrict__ Wg) {
    int t = blockIdx.x * 256 + threadIdx.x;   // 0 .. 2*128*128-1
    int which = t >> 14;                      // 0: Wc, 1: Wg
    int e = t & (Cc*Cc - 1);
    int o = e >> 7, c = e & 127;
    const float* W = which ? Wg : Wc;
    g_wT[which*Cc*Cc + c*Cc + o] = W[o*Cc + c];
}

// ------------------------- KNN (2 lanes/query, balanced grid) --------------
// Same structure as R11 with ONE change: staging stores are hand-predicated
// inline-PTX  @p st.shared.b64  instead of C++ if{} (ptxas wraps each C++
// if in BSSY/BSYNC, ~37 cyc each; 8 per iteration was the hidden latency).
// Staging address is a running shared-space u32 (addr += qf*8, SELP+IADD);
// the flush trigger compares addr against a precomputed threshold.
// Grid: 37 blocks/batch x 8 = 296 (2/SM everywhere). Block: 256 thr =
// 128 query slots x 2 lanes; QPBLK=111 (last block 100); idle slots run
// worst=-INF. All warp collectives on uniform control flow. Depth 20,
// trigger cnt>=12, vote every 8 (12+8=20 capacity-exact). Flush drains
// reduce_max(cnt) via the 21-deep FMNMX/SEL network (invalid -> +INF).
// worst shared across the lane pair via shfl-min. Final pair merge via
// register snapshot + early-break; even lane writes ix[1..20] (slot 0 self).
#define KNN_INF  3.402823466e38f
#define KTHR 256
#define KSTG 20
#define QPBLK 111
#define BPB 37

__device__ __forceinline__ void pair_ins(float (&ds)[21], int (&ix)[21],
                                         float cd, int ci) {
    #pragma unroll
    for (int s = 0; s < 21; ++s) {
        bool t   = cd < ds[s];               // strict: earlier insert wins ties
        float mn = fminf(cd, ds[s]);
        float mx = fmaxf(cd, ds[s]);
        int  ni  = t ? ci : ix[s];
        ci       = t ? ix[s] : ci;
        ds[s] = mn; ix[s] = ni; cd = mx;
    }
}

__device__ __forceinline__ unsigned long long dj_pack(float d, int j) {
    unsigned long long r;
    asm("mov.b64 %0, {%1, %2};" : "=l"(r) : "r"(j), "f"(d));
    return r;
}
__device__ __forceinline__ void dj_unpack(unsigned long long v, float& d, int& j) {
    asm("mov.b64 {%0, %1}, %2;" : "=r"(j), "=f"(d) : "l"(v));
}

// Predicated shared store, no BSSY/BSYNC (ptxas won't emit this from C++ if)
__device__ __forceinline__ void sts64_pred(unsigned addr, unsigned long long v, int p) {
    asm volatile("{\n\t"
                 ".reg .pred q;\n\t"
                 "setp.ne.b32 q, %2, 0;\n\t"
                 "@q st.shared.b64 [%0], %1;\n\t"
                 "}"
                 :: "r"(addr), "l"(v), "r"(p) : "memory");
}

__global__ __launch_bounds__(KTHR, 2) void knn_kernel(const float* __restrict__ xyz) {
    extern __shared__ float sraw[];
    float4* tile = (float4*)sraw;                              // Nn float4 (64KB)
    unsigned long long* stg = (unsigned long long*)(sraw + Nn*4);  // KTHR*(KSTG+1) u64

    int tid  = threadIdx.x;
    int half = tid & 1;                                // candidate parity
    int qloc = tid >> 1;                               // 0..127 (slots; QPBLK used)
    int bib  = blockIdx.x % BPB;                       // block-in-batch 0..36
    int b    = blockIdx.x / BPB;
    int qstart = bib * QPBLK;
    int qcount = min(QPBLK, Nn - qstart);
    const float* px = xyz + b * 3 * Nn;

    // pack this batch's xyz -> (x,y,z,|x|^2) tile
    for (int n = tid; n < Nn; n += KTHR) {
        float x = px[n], y = px[Nn + n], z = px[2*Nn + n];
        tile[n] = make_float4(x, y, z, fmaf(x, x, fmaf(y, y, z * z)));
    }
    __syncthreads();

    bool active = qloc < qcount;
    int selfn = qstart + (active ? qloc : 0);
    float4 me = tile[selfn];
    float mx = -2.f * me.x, my = -2.f * me.y, mz = -2.f * me.z;

    float ds[21]; int ix[21];
    #pragma unroll
    for (int s = 0; s < 21; ++s) { ds[s] = KNN_INF; ix[s] = 0; }
    float worst = active ? KNN_INF : -KNN_INF;         // idle: never qualifies
    unsigned long long* st = stg + tid * (KSTG + 1);

    unsigned a0;                                       // shared-space base addr
    asm("{ .reg .u64 t; cvta.to.shared.u64 t, %1; cvt.u32.u64 %0, t; }"
        : "=r"(a0) : "l"((void*)st));
    unsigned addr = a0;
    unsigned thr  = a0 + (KSTG - 8) * 8;               // trigger: cnt >= 12

    #pragma unroll 1
    for (int i0 = 0; i0 < Nn/2; i0 += 8) {
        // 8 candidates, predicated stores, running shared address
        #pragma unroll
        for (int u = 0; u < 8; ++u) {
            int j = (i0 + u) * 2 + half;
            float4 c = tile[j];
            float d = fmaf(mx, c.x, fmaf(my, c.y, fmaf(mz, c.z, c.w)));
            int qf = d < worst;
            sts64_pred(addr, dj_pack(d, j), qf);
            addr += qf * 8;
        }

        if (__any_sync(0xffffffffu, addr >= thr)) {
            int cnt = (int)(addr - a0) >> 3;
            int um = __reduce_max_sync(0xffffffffu, cnt);
            #pragma unroll 1
            for (int u = 0; u < um; ++u) {
                float vd; int vi;
                dj_unpack(st[u], vd, vi);
                pair_ins(ds, ix, (u < cnt) ? vd : KNN_INF, vi);
            }
            // collectives unconditional; activity gates only the select
            float wm = ds[20];
            float wp = __shfl_xor_sync(0xffffffffu, wm, 1);
            worst = active ? fminf(wm, wp) : -KNN_INF;
            addr = a0;
        }
    }
    {   // final drain
        int cnt = (int)(addr - a0) >> 3;
        int um = __reduce_max_sync(0xffffffffu, cnt);
        #pragma unroll 1
        for (int u = 0; u < um; ++u) {
            float vd; int vi;
            dj_unpack(st[u], vd, vi);
            pair_ins(ds, ix, (u < cnt) ? vd : KNN_INF, vi);
        }
    }

    // merge lane pair: snapshot partner's sorted list, insert w/ early break
    float od[21]; int oi[21];
    #pragma unroll
    for (int s = 0; s < 21; ++s) {
        od[s] = __shfl_xor_sync(0xffffffffu, ds[s], 1);
        oi[s] = __shfl_xor_sync(0xffffffffu, ix[s], 1);
    }
    #pragma unroll 1
    for (int s = 0; s < 21; ++s) {
        if (od[s] >= ds[20]) break;                    // od sorted: rest can't enter
        pair_ins(ds, ix, od[s], oi[s]);
    }

    if (half == 0 && active) {
        int gq = b * Nn + qstart + qloc;
        int base = b * Nn;
        #pragma unroll
        for (int s = 0; s < 20; ++s) g_knn[gq*Kk + s] = base + ix[s + 1];  // drop self
    }
}

// ------------------------- fused GEMM: [Wc;Wg] @ leaky(P) ------------------
// grid (N/128, B, 2); z=0 -> center [b][o][n] f32; z=1 -> g_hT [b][n][o] fp16
__global__ __launch_bounds__(256) void gemm_kernel(const float* __restrict__ points) {
    __shared__ __align__(16) float Ws[32][128];   // [c][o]
    __shared__ __align__(16) float Ps[32][128];   // [c][n]
    int b  = blockIdx.y;
    int n0 = blockIdx.x * 128;
    int which = blockIdx.z;
    const float* WT = g_wT + which * Cc * Cc;
    const float* P  = points + b * Cc * Nn;
    int tid = threadIdx.x;
    int tx = tid & 15, ty = tid >> 4;

    unsigned long long acc[8][4];                 // 8 rows x 4 fp32x2 col-pairs
    #pragma unroll
    for (int r = 0; r < 8; ++r)
        #pragma unroll
        for (int q = 0; q < 4; ++q) acc[r][q] = 0ull;

    for (int kc = 0; kc < Cc; kc += 32) {
        __syncthreads();
        #pragma unroll
        for (int i = 0; i < 4; ++i) {
            int f4 = tid + i * 256;               // 0..1023 float4 slots
            int c = f4 >> 5, n4 = f4 & 31;
            *(float4*)&Ws[c][n4*4] = *(const float4*)(WT + (kc + c)*Cc + n4*4);
            float4 pv = *(const float4*)(P + (kc + c)*Nn + n0 + n4*4);
            pv.x = fmaxf(pv.x, 0.f) + 0.01f * fminf(pv.x, 0.f);
            pv.y = fmaxf(pv.y, 0.f) + 0.01f * fminf(pv.y, 0.f);
            pv.z = fmaxf(pv.z, 0.f) + 0.01f * fminf(pv.z, 0.f);
            pv.w = fmaxf(pv.w, 0.f) + 0.01f * fminf(pv.w, 0.f);
            *(float4*)&Ps[c][n4*4] = pv;
        }
        __syncthreads();
        #pragma unroll
        for (int c = 0; c < 32; ++c) {
            float a[8];
            *(float4*)&a[0] = *(float4*)&Ws[c][ty*8];
            *(float4*)&a[4] = *(float4*)&Ws[c][ty*8 + 4];
            unsigned long long bp[4];
            *(ulonglong2*)&bp[0] = *(ulonglong2*)&Ps[c][tx*8];
            *(ulonglong2*)&bp[2] = *(ulonglong2*)&Ps[c][tx*8 + 4];
            #pragma unroll
            for (int r = 0; r < 8; ++r) {
                unsigned long long av;
                asm("mov.b64 %0, {%1, %1};" : "=l"(av) : "f"(a[r]));
                #pragma unroll
                for (int q = 0; q < 4; ++q)
                    asm("fma.rn.f32x2 %0, %1, %2, %0;"
                        : "+l"(acc[r][q]) : "l"(av), "l"(bp[q]));
            }
        }
    }

    union U { unsigned long long u; float2 f; };
    if (which == 0) {
        #pragma unroll
        for (int r = 0; r < 8; ++r) {
            int o = ty*8 + r;
            float v[8];
            #pragma unroll
            for (int q = 0; q < 4; ++q) { U t; t.u = acc[r][q]; v[2*q] = t.f.x; v[2*q+1] = t.f.y; }
            float* dst = g_center + (b*Cc + o)*Nn + n0 + tx*8;
            *(float4*)dst       = make_float4(v[0], v[1], v[2], v[3]);
            *(float4*)(dst + 4) = make_float4(v[4], v[5], v[6], v[7]);
        }
    } else {
        #pragma unroll
        for (int q = 0; q < 4; ++q) {
            float lo[8], hi[8];
            #pragma unroll
            for (int r = 0; r < 8; ++r) { U t; t.u = acc[r][q]; lo[r] = t.f.x; hi[r] = t.f.y; }
            int n = n0 + tx*8 + 2*q;
            union PK { __half2 h2[4]; uint4 u; } p0, p1;
            #pragma unroll
            for (int s = 0; s < 4; ++s) {
                p0.h2[s] = __floats2half2_rn(lo[2*s], lo[2*s+1]);
                p1.h2[s] = __floats2half2_rn(hi[2*s], hi[2*s+1]);
            }
            __half* d0 = g_hT + ((size_t)(b*Nn + n    ))*Cc + ty*8;
            __half* d1 = g_hT + ((size_t)(b*Nn + n + 1))*Cc + ty*8;
            *(uint4*)d0 = p0.u;
            *(uint4*)d1 = p1.u;
        }
    }
}

// ------------------------- combine: gather-sum + center + bias + residual --
__global__ __launch_bounds__(256) void combine_kernel(const float* __restrict__ points,
                                                      const float* __restrict__ bc,
                                                      const float* __restrict__ bg,
                                                      float* __restrict__ out) {
    __shared__ float sm[32][133];     // [n_local][o], pad 133 -> conflict-free transpose
    __shared__ int   sidx[32*20];
    int b  = blockIdx.y;
    int n0 = blockIdx.x * 32;
    int tid = threadIdx.x;

    for (int u = tid; u < 32*20; u += 256)
        sidx[u] = g_knn[(b*Nn + n0)*20 + u];
    __syncthreads();

    // phase A: neighbor gather-sum (fp16 payload, fp32 accumulate)
    int h = tid >> 6, o2 = tid & 63;          // 4 rows in flight, 64 half2-lanes
    for (int nl = h; nl < 32; nl += 4) {
        float ax = 0.f, ay = 0.f;
        #pragma unroll
        for (int k = 0; k < Kk; ++k) {
            int nb = sidx[nl*20 + k];          // global b*N+n index
            __half2 v = *(const __half2*)(g_hT + (size_t)nb*Cc + o2*2);
            float2 f = __half22float2(v);
            ax += f.x; ay += f.y;
        }
        sm[nl][o2*2]     = ax;
        sm[nl][o2*2 + 1] = ay;
    }
    __syncthreads();

    // phase B: transposed, coalesced write with center + bias + shortcut
    int w = tid >> 5, l = tid & 31;
    int n = n0 + l;
    #pragma unroll
    for (int oo = 0; oo < 16; ++oo) {
        int o2b = w + oo*8;
        int off = (b*Cc + o2b)*Nn + n;
        float biasv = fmaf(20.f, bg[o2b], bc[o2b]);
        out[off] = (sm[l][o2b] + g_center[off] + biasv) * (1.0f / 21.0f) + points[off];
    }
}

// ------------------------- launch -----------------------------------------
extern "C" void kernel_launch(void* const* d_in, const int* in_sizes, int n_in,
                              void* d_out, int out_size) {
    const float* xyz    = (const float*)d_in[0];
    const float* points = (const float*)d_in[1];
    const float* Wc     = (const float*)d_in[2];
    const float* bc     = (const float*)d_in[3];
    const float* Wg     = (const float*)d_in[4];
    const float* bg     = (const float*)d_in[5];
    float* out = (float*)d_out;

    int knn_smem = Nn*16 + KTHR*(KSTG+1)*8;
    cudaFuncSetAttribute(knn_kernel, cudaFuncAttributeMaxDynamicSharedMemorySize, knn_smem);

    prep_kernel<<<128, 256>>>(Wc, Wg);
    knn_kernel<<<Bb*BPB, KTHR, knn_smem>>>(xyz);
    gemm_kernel<<<dim3(Nn/128, Bb, 2), 256>>>(points);
    combine_kernel<<<dim3(Nn/32, Bb), 256>>>(points, bc, bg, out);
}